// round 14
// baseline (speedup 1.0000x reference)
#include <cuda_runtime.h>
#include <cuda_fp16.h>

#define D_MODEL 512
#define NHEAD   8
#define HD      64
#define BATCH   2
#define SEQ     2048
#define LOG2E   1.4426950408889634f
#define QSCALE  (0.125f * LOG2E)     // 1/sqrt(64) * log2(e), folded into Q

// ---------------- scratch ----------------
__device__ __half g_Q[BATCH*NHEAD*SEQ*HD];   // pre-scaled by QSCALE
__device__ __half g_K[BATCH*NHEAD*SEQ*HD];
__device__ __half g_V[BATCH*NHEAD*SEQ*HD];
__device__ float  g_cp[BATCH*NHEAD*SEQ];     // coord proj ×LOG2E
__device__ __half g_maskh[SEQ*SEQ];          // mask ×LOG2E, fp16
__device__ __half g_xh[BATCH*SEQ*D_MODEL];   // x in fp16
__device__ __half g_wh[3*D_MODEL*D_MODEL];   // qkv_w in fp16

// ---------------- helpers ----------------
static __device__ __forceinline__ void mma_f16(float d[4], const unsigned a[4],
                                               unsigned b0, unsigned b1) {
    asm volatile("mma.sync.aligned.m16n8k16.row.col.f32.f16.f16.f32 "
                 "{%0,%1,%2,%3},{%4,%5,%6,%7},{%8,%9},{%0,%1,%2,%3};"
                 : "+f"(d[0]), "+f"(d[1]), "+f"(d[2]), "+f"(d[3])
                 : "r"(a[0]), "r"(a[1]), "r"(a[2]), "r"(a[3]), "r"(b0), "r"(b1));
}
static __device__ __forceinline__ unsigned packh2(float a, float b) {
    __half2 h = __floats2half2_rn(a, b);
    return *reinterpret_cast<unsigned*>(&h);
}
static __device__ __forceinline__ unsigned smem_u32(const void* p) {
    return (unsigned)__cvta_generic_to_shared(p);
}
static __device__ __forceinline__ void ldsm_x4(unsigned& r0, unsigned& r1,
                                               unsigned& r2, unsigned& r3,
                                               unsigned addr) {
    asm volatile("ldmatrix.sync.aligned.m8n8.x4.shared.b16 {%0,%1,%2,%3}, [%4];"
                 : "=r"(r0), "=r"(r1), "=r"(r2), "=r"(r3) : "r"(addr));
}
static __device__ __forceinline__ void ldsm_x4t(unsigned& r0, unsigned& r1,
                                                unsigned& r2, unsigned& r3,
                                                unsigned addr) {
    asm volatile("ldmatrix.sync.aligned.m8n8.x4.trans.shared.b16 {%0,%1,%2,%3}, [%4];"
                 : "=r"(r0), "=r"(r1), "=r"(r2), "=r"(r3) : "r"(addr));
}
static __device__ __forceinline__ void cp16(unsigned dst, const void* src) {
    asm volatile("cp.async.cg.shared.global [%0], [%1], 16;"
                 :: "r"(dst), "l"(src));
}
#define CP_COMMIT() asm volatile("cp.async.commit_group;")
#define CP_WAIT(n)  asm volatile("cp.async.wait_group %0;" :: "n"(n))

// ---------------- prep kernels ----------------
__global__ void coord_proj_kernel(const float* __restrict__ coords,
                                  const float* __restrict__ rw) {
    int idx = blockIdx.x * blockDim.x + threadIdx.x;
    if (idx >= BATCH*NHEAD*SEQ) return;
    int n = idx & (SEQ - 1);
    int h = (idx >> 11) & 7;
    int b = idx >> 14;
    const float* c = coords + (b*SEQ + n)*3;
    const float* w = rw + h*3;
    g_cp[idx] = (c[0]*w[0] + c[1]*w[1] + c[2]*w[2]) * LOG2E;
}
__global__ void mask_prep_kernel(const float* __restrict__ mask) {
    int i = blockIdx.x * blockDim.x + threadIdx.x;
    float4 m = ((const float4*)mask)[i];
    __half2* dst = (__half2*)g_maskh;
    dst[i*2]     = __floats2half2_rn(m.x*LOG2E, m.y*LOG2E);
    dst[i*2 + 1] = __floats2half2_rn(m.z*LOG2E, m.w*LOG2E);
}
__global__ void cvt_h_kernel(const float* __restrict__ src, __half* dst, int n4) {
    int i = blockIdx.x * blockDim.x + threadIdx.x;
    if (i >= n4) return;
    float4 v = ((const float4*)src)[i];
    __half2* d = (__half2*)dst;
    d[i*2]     = __floats2half2_rn(v.x, v.y);
    d[i*2 + 1] = __floats2half2_rn(v.z, v.w);
}

// ---------------- QKV GEMM: fp16 mma, cp.async double buffer ------------
// 128x64 tile, K-chunk 64, 256 threads (8 warps x 16 rows).
#define GST 72
#define G_SMEM ((2*128*GST + 2*64*GST) * 2)     // 55296 bytes

__global__ __launch_bounds__(256)
void qkv_gemm_kernel(const float* __restrict__ bias) {
    extern __shared__ __align__(16) char smraw[];
    __half* Xs = (__half*)smraw;                 // 2 stages x 128*GST
    __half* Ws = (__half*)smraw + 2*128*GST;     // 2 stages x 64*GST
    const int m0 = blockIdx.y * 128, o0 = blockIdx.x * 64;
    const int tid = threadIdx.x, lane = tid & 31, warp = tid >> 5;
    const int g = lane >> 2, t = lane & 3, wm = warp * 16;
    const int lrow = lane & 15, lcol = (lane >> 4) << 3;

    const __half* xg = g_xh + (size_t)m0 * D_MODEL;
    const __half* wg = g_wh + (size_t)o0 * D_MODEL;

    auto issue = [&](int ch, int stg) {
        int kb = ch * 64;
        #pragma unroll
        for (int s = 0; s < 4; s++) {
            int slot = tid + s*256;                 // X: 128 rows x 8
            int row = slot >> 3, c8 = slot & 7;
            cp16(smem_u32(&Xs[stg*128*GST + row*GST + c8*8]),
                 xg + (size_t)row*D_MODEL + kb + c8*8);
        }
        #pragma unroll
        for (int s = 0; s < 2; s++) {
            int slot = tid + s*256;                 // W: 64 rows x 8
            int row = slot >> 3, c8 = slot & 7;
            cp16(smem_u32(&Ws[stg*64*GST + row*GST + c8*8]),
                 wg + (size_t)row*D_MODEL + kb + c8*8);
        }
    };

    float c[8][4] = {};
    issue(0, 0); CP_COMMIT();

    for (int ch = 0; ch < 8; ch++) {
        int cb = ch & 1;
        if (ch < 7) { issue(ch + 1, cb ^ 1); CP_COMMIT(); CP_WAIT(1); }
        else        { CP_WAIT(0); }
        __syncthreads();
        const __half* X = Xs + cb*128*GST;
        const __half* W = Ws + cb*64*GST;
        #pragma unroll
        for (int kk = 0; kk < 4; kk++) {
            unsigned a[4];
            ldsm_x4(a[0], a[1], a[2], a[3],
                    smem_u32(&X[(wm + lrow)*GST + kk*16 + lcol]));
            #pragma unroll
            for (int j = 0; j < 4; j++) {
                unsigned r0, r1, r2, r3;
                ldsm_x4(r0, r1, r2, r3,
                        smem_u32(&W[(j*16 + lrow)*GST + kk*16 + lcol]));
                mma_f16(c[2*j],     a, r0, r2);
                mma_f16(c[2*j + 1], a, r1, r3);
            }
        }
        __syncthreads();
    }

    const int which = o0 >> 9;               // 0=q 1=k 2=v
    const int h = (o0 >> 6) & 7;
    const float sc = (which == 0) ? QSCALE : 1.0f;
    __half* dstbase = (which == 0) ? g_Q : (which == 1 ? g_K : g_V);
    #pragma unroll
    for (int r = 0; r < 2; r++) {
        int m = m0 + wm + g + r*8;
        int b = m >> 11, n = m & 2047;
        __half* dst = dstbase + ((size_t)(b*NHEAD + h)*SEQ + n)*HD;
        #pragma unroll
        for (int j = 0; j < 8; j++) {
            int c0 = j*8 + t*2;
            float2 bi = *(const float2*)&bias[o0 + c0];
            *(__half2*)&dst[c0] = __floats2half2_rn(
                (c[j][r*2 + 0] + bi.x) * sc,
                (c[j][r*2 + 1] + bi.y) * sc);
        }
    }
}

// ---------------- flash attention: cp.async pipeline, ones-column l ------
#define ST 72
#define F_SMEM ((128*ST + 2*64*ST + 2*64*ST)*2 + 2*64*4)   // 55808 bytes
#define ONE2 0x3C003C00u

__global__ __launch_bounds__(256, 2)
void flash_kernel(float* __restrict__ out) {
    extern __shared__ __align__(16) char smraw[];
    __half* Qh  = (__half*)smraw;                 // 128*ST
    __half* Kh  = Qh + 128*ST;                    // 2 stages x 64*ST
    __half* Vh  = Kh + 2*64*ST;                   // 2 stages x 64*ST
    float*  cpk = (float*)(Vh + 2*64*ST);         // 2 stages x 64

    const int b = blockIdx.z, h = blockIdx.y, q0 = blockIdx.x * 128;
    const int tid = threadIdx.x, lane = tid & 31, warp = tid >> 5;
    const int g = lane >> 2, t = lane & 3, wm = warp * 16;
    const int lrow = lane & 15, lcol = (lane >> 4) << 3;

    const size_t base = (size_t)(b*NHEAD + h) * SEQ;
    const __half* Qg  = g_Q + (base + q0) * HD;
    const __half* Kg  = g_K + base * HD;
    const __half* Vg  = g_V + base * HD;
    const float*  cpb = g_cp + base;

    auto issue_kv = [&](int kt, int stg) {
        int k0 = kt * 64;
        #pragma unroll
        for (int s = 0; s < 2; s++) {
            int slot = tid + s*256;                 // 64 rows x 8
            int row = slot >> 3, c8 = slot & 7;
            cp16(smem_u32(&Kh[stg*64*ST + row*ST + c8*8]),
                 Kg + (size_t)(k0+row)*HD + c8*8);
            cp16(smem_u32(&Vh[stg*64*ST + row*ST + c8*8]),
                 Vg + (size_t)(k0+row)*HD + c8*8);
        }
        if (tid < 16) cp16(smem_u32(&cpk[stg*64 + tid*4]), cpb + k0 + tid*4);
    };

    // stage Q + first KV tile (group 0)
    #pragma unroll
    for (int s = 0; s < 4; s++) {
        int slot = tid + s*256;
        int row = slot >> 3, c8 = slot & 7;
        cp16(smem_u32(&Qh[row*ST + c8*8]), Qg + (size_t)row*HD + c8*8);
    }
    issue_kv(0, 0); CP_COMMIT();

    float o[8][4] = {};
    float l_acc[4] = {};
    float m_lo = -1e30f, m_hi = -1e30f;
    const int r_lo = q0 + wm + g;
    const __half* mrow_lo = g_maskh + (size_t)r_lo * SEQ;
    const __half* mrow_hi = g_maskh + (size_t)(r_lo + 8) * SEQ;

    for (int kt = 0; kt < SEQ/64; kt++) {
        const int k0 = kt * 64;
        const int cb = kt & 1;
        if (kt < SEQ/64 - 1) { issue_kv(kt + 1, cb ^ 1); CP_COMMIT(); CP_WAIT(1); }
        else                 { CP_WAIT(0); }
        __syncthreads();

        // prefetch mask tile into registers (L2 latency hidden behind mma)
        unsigned mlv[8], mhv[8];
        #pragma unroll
        for (int j = 0; j < 8; j++) {
            mlv[j] = *(const unsigned*)&mrow_lo[k0 + j*8 + t*2];
            mhv[j] = *(const unsigned*)&mrow_hi[k0 + j*8 + t*2];
        }

        const __half* K = Kh + cb*64*ST;
        const __half* V = Vh + cb*64*ST;
        const float*  cp = cpk + cb*64;

        // ---- S = Q·K^T ----
        float sreg[8][4] = {};
        #pragma unroll
        for (int kk = 0; kk < 4; kk++) {
            unsigned qa[4];
            ldsm_x4(qa[0], qa[1], qa[2], qa[3],
                    smem_u32(&Qh[(wm + lrow)*ST + kk*16 + lcol]));
            #pragma unroll
            for (int j = 0; j < 4; j++) {
                unsigned r0, r1, r2, r3;
                ldsm_x4(r0, r1, r2, r3,
                        smem_u32(&K[(j*16 + lrow)*ST + kk*16 + lcol]));
                mma_f16(sreg[2*j],     qa, r0, r2);
                mma_f16(sreg[2*j + 1], qa, r1, r3);
            }
        }

        // ---- bias: + mask(×LOG2E fp16) - cp_k ----
        #pragma unroll
        for (int j = 0; j < 8; j++) {
            int c0 = j*8 + t*2;
            float2 ml = __half22float2(*(const __half2*)&mlv[j]);
            float2 mh = __half22float2(*(const __half2*)&mhv[j]);
            float2 cpv = *(const float2*)&cp[c0];
            sreg[j][0] += ml.x - cpv.x;
            sreg[j][1] += ml.y - cpv.y;
            sreg[j][2] += mh.x - cpv.x;
            sreg[j][3] += mh.y - cpv.y;
        }

        // ---- online softmax (registers + quad shfl) ----
        float tl = -1e30f, th = -1e30f;
        #pragma unroll
        for (int j = 0; j < 8; j++) {
            tl = fmaxf(tl, fmaxf(sreg[j][0], sreg[j][1]));
            th = fmaxf(th, fmaxf(sreg[j][2], sreg[j][3]));
        }
        tl = fmaxf(tl, __shfl_xor_sync(0xffffffffu, tl, 1));
        tl = fmaxf(tl, __shfl_xor_sync(0xffffffffu, tl, 2));
        th = fmaxf(th, __shfl_xor_sync(0xffffffffu, th, 1));
        th = fmaxf(th, __shfl_xor_sync(0xffffffffu, th, 2));
        float mnl = fmaxf(m_lo, tl), mnh = fmaxf(m_hi, th);
        float al = exp2f(m_lo - mnl), ah = exp2f(m_hi - mnh);
        m_lo = mnl; m_hi = mnh;
        #pragma unroll
        for (int j = 0; j < 8; j++) {
            sreg[j][0] = exp2f(sreg[j][0] - mnl);
            sreg[j][1] = exp2f(sreg[j][1] - mnl);
            sreg[j][2] = exp2f(sreg[j][2] - mnh);
            sreg[j][3] = exp2f(sreg[j][3] - mnh);
            o[j][0] *= al; o[j][1] *= al; o[j][2] *= ah; o[j][3] *= ah;
        }
        l_acc[0] *= al; l_acc[1] *= al; l_acc[2] *= ah; l_acc[3] *= ah;

        // ---- O += P·V ; l += P·1 (ones-column mma, exact) ----
        #pragma unroll
        for (int jp = 0; jp < 4; jp++) {
            unsigned pa[4];
            pa[0] = packh2(sreg[2*jp][0],   sreg[2*jp][1]);
            pa[1] = packh2(sreg[2*jp][2],   sreg[2*jp][3]);
            pa[2] = packh2(sreg[2*jp+1][0], sreg[2*jp+1][1]);
            pa[3] = packh2(sreg[2*jp+1][2], sreg[2*jp+1][3]);
            #pragma unroll
            for (int np = 0; np < 4; np++) {
                unsigned r0, r1, r2, r3;
                ldsm_x4t(r0, r1, r2, r3,
                         smem_u32(&V[(jp*16 + lrow)*ST + np*16 + lcol]));
                mma_f16(o[2*np],     pa, r0, r1);
                mma_f16(o[2*np + 1], pa, r2, r3);
            }
            mma_f16(l_acc, pa, ONE2, ONE2);
        }
        __syncthreads();
    }

    // ---- epilogue (l_acc holds full row sums; no shuffles needed) ----
    float il = 1.f / l_acc[0], ih = 1.f / l_acc[2];
    #pragma unroll
    for (int j = 0; j < 8; j++) {
        float2 v0 = { o[j][0]*il, o[j][1]*il };
        float2 v1 = { o[j][2]*ih, o[j][3]*ih };
        size_t off = ((size_t)b*SEQ + r_lo)*D_MODEL + h*HD + j*8 + t*2;
        *(float2*)&out[off] = v0;
        *(float2*)&out[off + 8*D_MODEL] = v1;
    }
}

// ---------------- launch ----------------
extern "C" void kernel_launch(void* const* d_in, const int* in_sizes, int n_in,
                              void* d_out, int out_size) {
    const float* x      = (const float*)d_in[0];
    const float* coords = (const float*)d_in[1];
    const float* mask   = (const float*)d_in[2];
    const float* qkv_w  = (const float*)d_in[3];
    const float* qkv_b  = (const float*)d_in[4];
    const float* rw     = (const float*)d_in[5];
    float* out = (float*)d_out;

    coord_proj_kernel<<<(BATCH*NHEAD*SEQ + 255)/256, 256>>>(coords, rw);
    mask_prep_kernel<<<(SEQ*SEQ/4 + 255)/256, 256>>>(mask);

    __half* xh; cudaGetSymbolAddress((void**)&xh, g_xh);
    __half* wh; cudaGetSymbolAddress((void**)&wh, g_wh);
    int nx4 = BATCH*SEQ*D_MODEL/4, nw4 = 3*D_MODEL*D_MODEL/4;
    cvt_h_kernel<<<(nx4 + 255)/256, 256>>>(x, xh, nx4);
    cvt_h_kernel<<<(nw4 + 255)/256, 256>>>(qkv_w, wh, nw4);

    cudaFuncSetAttribute(qkv_gemm_kernel,
                         cudaFuncAttributeMaxDynamicSharedMemorySize, G_SMEM);
    dim3 ggrid(3*D_MODEL/64, BATCH*SEQ/128);
    qkv_gemm_kernel<<<ggrid, 256, G_SMEM>>>(qkv_b);

    cudaFuncSetAttribute(flash_kernel,
                         cudaFuncAttributeMaxDynamicSharedMemorySize, F_SMEM);
    dim3 fgrid(SEQ/128, NHEAD, BATCH);
    flash_kernel<<<fgrid, 256, F_SMEM>>>(out);
}

// round 15
// speedup vs baseline: 1.0752x; 1.0752x over previous
#include <cuda_runtime.h>
#include <cuda_fp16.h>

#define D_MODEL 512
#define NHEAD   8
#define HD      64
#define BATCH   2
#define SEQ     2048
#define LOG2E   1.4426950408889634f
#define QSCALE  (0.125f * LOG2E)     // 1/sqrt(64) * log2(e), folded into Q

// ---------------- scratch ----------------
__device__ __half g_Q[BATCH*NHEAD*SEQ*HD];   // pre-scaled by QSCALE
__device__ __half g_K[BATCH*NHEAD*SEQ*HD];
__device__ __half g_V[BATCH*NHEAD*SEQ*HD];
__device__ float  g_cp[BATCH*NHEAD*SEQ];     // coord proj ×LOG2E
__device__ __half g_maskh[SEQ*SEQ];          // mask ×LOG2E, fp16
__device__ __half g_xh[BATCH*SEQ*D_MODEL];   // x in fp16
__device__ __half g_wh[3*D_MODEL*D_MODEL];   // qkv_w in fp16

// ---------------- helpers ----------------
static __device__ __forceinline__ void mma_f16(float d[4], const unsigned a[4],
                                               unsigned b0, unsigned b1) {
    asm volatile("mma.sync.aligned.m16n8k16.row.col.f32.f16.f16.f32 "
                 "{%0,%1,%2,%3},{%4,%5,%6,%7},{%8,%9},{%0,%1,%2,%3};"
                 : "+f"(d[0]), "+f"(d[1]), "+f"(d[2]), "+f"(d[3])
                 : "r"(a[0]), "r"(a[1]), "r"(a[2]), "r"(a[3]), "r"(b0), "r"(b1));
}
static __device__ __forceinline__ unsigned packh2(float a, float b) {
    __half2 h = __floats2half2_rn(a, b);
    return *reinterpret_cast<unsigned*>(&h);
}
static __device__ __forceinline__ unsigned smem_u32(const void* p) {
    return (unsigned)__cvta_generic_to_shared(p);
}
static __device__ __forceinline__ void ldsm_x4(unsigned& r0, unsigned& r1,
                                               unsigned& r2, unsigned& r3,
                                               unsigned addr) {
    asm volatile("ldmatrix.sync.aligned.m8n8.x4.shared.b16 {%0,%1,%2,%3}, [%4];"
                 : "=r"(r0), "=r"(r1), "=r"(r2), "=r"(r3) : "r"(addr));
}
static __device__ __forceinline__ void ldsm_x4t(unsigned& r0, unsigned& r1,
                                                unsigned& r2, unsigned& r3,
                                                unsigned addr) {
    asm volatile("ldmatrix.sync.aligned.m8n8.x4.trans.shared.b16 {%0,%1,%2,%3}, [%4];"
                 : "=r"(r0), "=r"(r1), "=r"(r2), "=r"(r3) : "r"(addr));
}
static __device__ __forceinline__ void cp16(unsigned dst, const void* src) {
    asm volatile("cp.async.cg.shared.global [%0], [%1], 16;"
                 :: "r"(dst), "l"(src));
}
#define CP_COMMIT() asm volatile("cp.async.commit_group;")
#define CP_WAIT(n)  asm volatile("cp.async.wait_group %0;" :: "n"(n))

// ---------------- fused prep kernel (single launch) ----------------
#define MASK4 (SEQ*SEQ/4)                    // 1048576
#define X4    (BATCH*SEQ*D_MODEL/4)          // 524288
#define W4    (3*D_MODEL*D_MODEL/4)          // 196608
#define NCP   (BATCH*NHEAD*SEQ)              // 32768
#define PREP_TOT (MASK4 + X4 + W4 + NCP)

__global__ void prep_kernel(const float* __restrict__ mask,
                            const float* __restrict__ x,
                            const float* __restrict__ w,
                            const float* __restrict__ coords,
                            const float* __restrict__ rw) {
    int i = blockIdx.x * blockDim.x + threadIdx.x;
    if (i < MASK4) {
        float4 m = ((const float4*)mask)[i];
        __half2* dst = (__half2*)g_maskh;
        dst[i*2]     = __floats2half2_rn(m.x*LOG2E, m.y*LOG2E);
        dst[i*2 + 1] = __floats2half2_rn(m.z*LOG2E, m.w*LOG2E);
        return;
    }
    i -= MASK4;
    if (i < X4) {
        float4 v = ((const float4*)x)[i];
        __half2* d = (__half2*)g_xh;
        d[i*2]     = __floats2half2_rn(v.x, v.y);
        d[i*2 + 1] = __floats2half2_rn(v.z, v.w);
        return;
    }
    i -= X4;
    if (i < W4) {
        float4 v = ((const float4*)w)[i];
        __half2* d = (__half2*)g_wh;
        d[i*2]     = __floats2half2_rn(v.x, v.y);
        d[i*2 + 1] = __floats2half2_rn(v.z, v.w);
        return;
    }
    i -= W4;
    if (i < NCP) {
        int n = i & (SEQ - 1);
        int h = (i >> 11) & 7;
        int b = i >> 14;
        const float* c = coords + (b*SEQ + n)*3;
        const float* wv = rw + h*3;
        g_cp[i] = (c[0]*wv[0] + c[1]*wv[1] + c[2]*wv[2]) * LOG2E;
    }
}

// ---------------- QKV GEMM: fp16 mma, cp.async double buffer ------------
#define GST 72
#define G_SMEM ((2*128*GST + 2*64*GST) * 2)     // 55296 bytes

__global__ __launch_bounds__(256)
void qkv_gemm_kernel(const float* __restrict__ bias) {
    extern __shared__ __align__(16) char smraw[];
    __half* Xs = (__half*)smraw;
    __half* Ws = (__half*)smraw + 2*128*GST;
    const int m0 = blockIdx.y * 128, o0 = blockIdx.x * 64;
    const int tid = threadIdx.x, lane = tid & 31, warp = tid >> 5;
    const int g = lane >> 2, t = lane & 3, wm = warp * 16;
    const int lrow = lane & 15, lcol = (lane >> 4) << 3;

    const __half* xg = g_xh + (size_t)m0 * D_MODEL;
    const __half* wg = g_wh + (size_t)o0 * D_MODEL;

    auto issue = [&](int ch, int stg) {
        int kb = ch * 64;
        #pragma unroll
        for (int s = 0; s < 4; s++) {
            int slot = tid + s*256;
            int row = slot >> 3, c8 = slot & 7;
            cp16(smem_u32(&Xs[stg*128*GST + row*GST + c8*8]),
                 xg + (size_t)row*D_MODEL + kb + c8*8);
        }
        #pragma unroll
        for (int s = 0; s < 2; s++) {
            int slot = tid + s*256;
            int row = slot >> 3, c8 = slot & 7;
            cp16(smem_u32(&Ws[stg*64*GST + row*GST + c8*8]),
                 wg + (size_t)row*D_MODEL + kb + c8*8);
        }
    };

    float c[8][4] = {};
    issue(0, 0); CP_COMMIT();

    for (int ch = 0; ch < 8; ch++) {
        int cb = ch & 1;
        if (ch < 7) { issue(ch + 1, cb ^ 1); CP_COMMIT(); CP_WAIT(1); }
        else        { CP_WAIT(0); }
        __syncthreads();
        const __half* X = Xs + cb*128*GST;
        const __half* W = Ws + cb*64*GST;
        #pragma unroll
        for (int kk = 0; kk < 4; kk++) {
            unsigned a[4];
            ldsm_x4(a[0], a[1], a[2], a[3],
                    smem_u32(&X[(wm + lrow)*GST + kk*16 + lcol]));
            #pragma unroll
            for (int j = 0; j < 4; j++) {
                unsigned r0, r1, r2, r3;
                ldsm_x4(r0, r1, r2, r3,
                        smem_u32(&W[(j*16 + lrow)*GST + kk*16 + lcol]));
                mma_f16(c[2*j],     a, r0, r2);
                mma_f16(c[2*j + 1], a, r1, r3);
            }
        }
        __syncthreads();
    }

    const int which = o0 >> 9;               // 0=q 1=k 2=v
    const int h = (o0 >> 6) & 7;
    const float sc = (which == 0) ? QSCALE : 1.0f;
    __half* dstbase = (which == 0) ? g_Q : (which == 1 ? g_K : g_V);
    #pragma unroll
    for (int r = 0; r < 2; r++) {
        int m = m0 + wm + g + r*8;
        int b = m >> 11, n = m & 2047;
        __half* dst = dstbase + ((size_t)(b*NHEAD + h)*SEQ + n)*HD;
        #pragma unroll
        for (int j = 0; j < 8; j++) {
            int c0 = j*8 + t*2;
            float2 bi = *(const float2*)&bias[o0 + c0];
            *(__half2*)&dst[c0] = __floats2half2_rn(
                (c[j][r*2 + 0] + bi.x) * sc,
                (c[j][r*2 + 1] + bi.y) * sc);
        }
    }
}

// ---------------- flash attention: Q in regs, 3-stage pipe, 1 sync/tile --
#define ST   72
#define NSTG 3
#define NT   (SEQ/64)
// stage s: K rows [0,64) at s*128*ST, V rows at s*128*ST + 64*ST
#define F_SMEM ((NSTG*128*ST)*2 + NSTG*64*4)   // 55296 + 768 = 56064 bytes
#define ONE2 0x3C003C00u

__global__ __launch_bounds__(256, 2)
void flash_kernel(float* __restrict__ out) {
    extern __shared__ __align__(16) char smraw[];
    __half* KV  = (__half*)smraw;                  // NSTG * 128*ST
    float*  cpk = (float*)(KV + NSTG*128*ST);      // NSTG * 64

    const int b = blockIdx.z, h = blockIdx.y, q0 = blockIdx.x * 128;
    const int tid = threadIdx.x, lane = tid & 31, warp = tid >> 5;
    const int g = lane >> 2, t = lane & 3, wm = warp * 16;
    const int lrow = lane & 15, lcol = (lane >> 4) << 3;

    const size_t base = (size_t)(b*NHEAD + h) * SEQ;
    const __half* Qg  = g_Q + (base + q0) * HD;
    const __half* Kg  = g_K + base * HD;
    const __half* Vg  = g_V + base * HD;
    const float*  cpb = g_cp + base;

    // ---- stage Q through stage-0 smem, hoist fragments to registers ----
    #pragma unroll
    for (int s = 0; s < 4; s++) {
        int slot = tid + s*256;
        int row = slot >> 3, c8 = slot & 7;
        cp16(smem_u32(&KV[row*ST + c8*8]), Qg + (size_t)row*HD + c8*8);
    }
    CP_COMMIT(); CP_WAIT(0);
    __syncthreads();
    unsigned qa[4][4];
    #pragma unroll
    for (int kk = 0; kk < 4; kk++)
        ldsm_x4(qa[kk][0], qa[kk][1], qa[kk][2], qa[kk][3],
                smem_u32(&KV[(wm + lrow)*ST + kk*16 + lcol]));
    __syncthreads();

    auto issue_kv = [&](int kt, int stg) {
        int k0 = kt * 64;
        __half* Kh = KV + stg*128*ST;
        __half* Vh = Kh + 64*ST;
        #pragma unroll
        for (int s = 0; s < 2; s++) {
            int slot = tid + s*256;
            int row = slot >> 3, c8 = slot & 7;
            cp16(smem_u32(&Kh[row*ST + c8*8]), Kg + (size_t)(k0+row)*HD + c8*8);
            cp16(smem_u32(&Vh[row*ST + c8*8]), Vg + (size_t)(k0+row)*HD + c8*8);
        }
        if (tid < 16) cp16(smem_u32(&cpk[stg*64 + tid*4]), cpb + k0 + tid*4);
    };

    issue_kv(0, 0); CP_COMMIT();
    issue_kv(1, 1); CP_COMMIT();

    float o[8][4] = {};
    float l_acc[4] = {};
    float m_lo = -1e30f, m_hi = -1e30f;
    const int r_lo = q0 + wm + g;
    const __half* mrow_lo = g_maskh + (size_t)r_lo * SEQ;
    const __half* mrow_hi = g_maskh + (size_t)(r_lo + 8) * SEQ;

    for (int kt = 0; kt < NT; kt++) {
        const int k0 = kt * 64;
        const int stg = kt % NSTG;
        if (kt < NT - 1) { CP_WAIT(1); } else { CP_WAIT(0); }
        __syncthreads();                        // all done reading stage (kt-1)%3
        if (kt + 2 < NT) { issue_kv(kt + 2, (kt + 2) % NSTG); CP_COMMIT(); }

        // prefetch mask tile into registers
        unsigned mlv[8], mhv[8];
        #pragma unroll
        for (int j = 0; j < 8; j++) {
            mlv[j] = *(const unsigned*)&mrow_lo[k0 + j*8 + t*2];
            mhv[j] = *(const unsigned*)&mrow_hi[k0 + j*8 + t*2];
        }

        const __half* K = KV + stg*128*ST;
        const __half* V = K + 64*ST;
        const float*  cp = cpk + stg*64;

        // ---- S = Q·K^T (Q frags already in registers) ----
        float sreg[8][4] = {};
        #pragma unroll
        for (int kk = 0; kk < 4; kk++) {
            #pragma unroll
            for (int j = 0; j < 4; j++) {
                unsigned r0, r1, r2, r3;
                ldsm_x4(r0, r1, r2, r3,
                        smem_u32(&K[(j*16 + lrow)*ST + kk*16 + lcol]));
                mma_f16(sreg[2*j],     qa[kk], r0, r2);
                mma_f16(sreg[2*j + 1], qa[kk], r1, r3);
            }
        }

        // ---- bias: + mask(×LOG2E fp16) - cp_k ----
        #pragma unroll
        for (int j = 0; j < 8; j++) {
            int c0 = j*8 + t*2;
            float2 ml = __half22float2(*(const __half2*)&mlv[j]);
            float2 mh = __half22float2(*(const __half2*)&mhv[j]);
            float2 cpv = *(const float2*)&cp[c0];
            sreg[j][0] += ml.x - cpv.x;
            sreg[j][1] += ml.y - cpv.y;
            sreg[j][2] += mh.x - cpv.x;
            sreg[j][3] += mh.y - cpv.y;
        }

        // ---- online softmax (registers + quad shfl) ----
        float tl = -1e30f, th = -1e30f;
        #pragma unroll
        for (int j = 0; j < 8; j++) {
            tl = fmaxf(tl, fmaxf(sreg[j][0], sreg[j][1]));
            th = fmaxf(th, fmaxf(sreg[j][2], sreg[j][3]));
        }
        tl = fmaxf(tl, __shfl_xor_sync(0xffffffffu, tl, 1));
        tl = fmaxf(tl, __shfl_xor_sync(0xffffffffu, tl, 2));
        th = fmaxf(th, __shfl_xor_sync(0xffffffffu, th, 1));
        th = fmaxf(th, __shfl_xor_sync(0xffffffffu, th, 2));
        float mnl = fmaxf(m_lo, tl), mnh = fmaxf(m_hi, th);
        float al = exp2f(m_lo - mnl), ah = exp2f(m_hi - mnh);
        m_lo = mnl; m_hi = mnh;
        #pragma unroll
        for (int j = 0; j < 8; j++) {
            sreg[j][0] = exp2f(sreg[j][0] - mnl);
            sreg[j][1] = exp2f(sreg[j][1] - mnl);
            sreg[j][2] = exp2f(sreg[j][2] - mnh);
            sreg[j][3] = exp2f(sreg[j][3] - mnh);
            o[j][0] *= al; o[j][1] *= al; o[j][2] *= ah; o[j][3] *= ah;
        }
        l_acc[0] *= al; l_acc[1] *= al; l_acc[2] *= ah; l_acc[3] *= ah;

        // ---- O += P·V ; l += P·1 (ones-column mma, exact) ----
        #pragma unroll
        for (int jp = 0; jp < 4; jp++) {
            unsigned pa[4];
            pa[0] = packh2(sreg[2*jp][0],   sreg[2*jp][1]);
            pa[1] = packh2(sreg[2*jp][2],   sreg[2*jp][3]);
            pa[2] = packh2(sreg[2*jp+1][0], sreg[2*jp+1][1]);
            pa[3] = packh2(sreg[2*jp+1][2], sreg[2*jp+1][3]);
            #pragma unroll
            for (int np = 0; np < 4; np++) {
                unsigned r0, r1, r2, r3;
                ldsm_x4t(r0, r1, r2, r3,
                         smem_u32(&V[(jp*16 + lrow)*ST + np*16 + lcol]));
                mma_f16(o[2*np],     pa, r0, r1);
                mma_f16(o[2*np + 1], pa, r2, r3);
            }
            mma_f16(l_acc, pa, ONE2, ONE2);
        }
        // no end-of-tile sync: next iteration's start sync fences reuse
    }

    // ---- epilogue ----
    float il = 1.f / l_acc[0], ih = 1.f / l_acc[2];
    #pragma unroll
    for (int j = 0; j < 8; j++) {
        float2 v0 = { o[j][0]*il, o[j][1]*il };
        float2 v1 = { o[j][2]*ih, o[j][3]*ih };
        size_t off = ((size_t)b*SEQ + r_lo)*D_MODEL + h*HD + j*8 + t*2;
        *(float2*)&out[off] = v0;
        *(float2*)&out[off + 8*D_MODEL] = v1;
    }
}

// ---------------- launch ----------------
extern "C" void kernel_launch(void* const* d_in, const int* in_sizes, int n_in,
                              void* d_out, int out_size) {
    const float* x      = (const float*)d_in[0];
    const float* coords = (const float*)d_in[1];
    const float* mask   = (const float*)d_in[2];
    const float* qkv_w  = (const float*)d_in[3];
    const float* qkv_b  = (const float*)d_in[4];
    const float* rw     = (const float*)d_in[5];
    float* out = (float*)d_out;

    prep_kernel<<<(PREP_TOT + 255)/256, 256>>>(mask, x, qkv_w, coords, rw);

    cudaFuncSetAttribute(qkv_gemm_kernel,
                         cudaFuncAttributeMaxDynamicSharedMemorySize, G_SMEM);
    dim3 ggrid(3*D_MODEL/64, BATCH*SEQ/128);
    qkv_gemm_kernel<<<ggrid, 256, G_SMEM>>>(qkv_b);

    cudaFuncSetAttribute(flash_kernel,
                         cudaFuncAttributeMaxDynamicSharedMemorySize, F_SMEM);
    dim3 fgrid(SEQ/128, NHEAD, BATCH);
    flash_kernel<<<fgrid, 256, F_SMEM>>>(out);
}

// round 16
// speedup vs baseline: 1.2213x; 1.1358x over previous
#include <cuda_runtime.h>
#include <cuda_fp16.h>

#define D_MODEL 512
#define NHEAD   8
#define HD      64
#define BATCH   2
#define SEQ     2048
#define LOG2E   1.4426950408889634f
#define QSCALE  (0.125f * LOG2E)     // 1/sqrt(64) * log2(e), folded into Q

// ---------------- scratch ----------------
__device__ __half g_Q[BATCH*NHEAD*SEQ*HD];   // pre-scaled by QSCALE
__device__ __half g_K[BATCH*NHEAD*SEQ*HD];
__device__ __half g_V[BATCH*NHEAD*SEQ*HD];
__device__ float  g_cp[BATCH*NHEAD*SEQ];     // coord proj ×LOG2E
// mask ×LOG2E, fp16, FRAGMENT-ORDERED: half2 index = q*1024 + kt*32 + t*8 + j
// (original col = kt*64 + j*8 + t*2) -> each thread's 8 half2 per tile are 2 uint4
__device__ __half g_maskh[SEQ*SEQ];
__device__ __half g_xh[BATCH*SEQ*D_MODEL];   // x in fp16
__device__ __half g_wh[3*D_MODEL*D_MODEL];   // qkv_w in fp16

// ---------------- helpers ----------------
static __device__ __forceinline__ void mma_f16(float d[4], const unsigned a[4],
                                               unsigned b0, unsigned b1) {
    asm volatile("mma.sync.aligned.m16n8k16.row.col.f32.f16.f16.f32 "
                 "{%0,%1,%2,%3},{%4,%5,%6,%7},{%8,%9},{%0,%1,%2,%3};"
                 : "+f"(d[0]), "+f"(d[1]), "+f"(d[2]), "+f"(d[3])
                 : "r"(a[0]), "r"(a[1]), "r"(a[2]), "r"(a[3]), "r"(b0), "r"(b1));
}
static __device__ __forceinline__ unsigned smem_u32(const void* p) {
    return (unsigned)__cvta_generic_to_shared(p);
}
static __device__ __forceinline__ void ldsm_x4(unsigned& r0, unsigned& r1,
                                               unsigned& r2, unsigned& r3,
                                               unsigned addr) {
    asm volatile("ldmatrix.sync.aligned.m8n8.x4.shared.b16 {%0,%1,%2,%3}, [%4];"
                 : "=r"(r0), "=r"(r1), "=r"(r2), "=r"(r3) : "r"(addr));
}
static __device__ __forceinline__ void ldsm_x4t(unsigned& r0, unsigned& r1,
                                                unsigned& r2, unsigned& r3,
                                                unsigned addr) {
    asm volatile("ldmatrix.sync.aligned.m8n8.x4.trans.shared.b16 {%0,%1,%2,%3}, [%4];"
                 : "=r"(r0), "=r"(r1), "=r"(r2), "=r"(r3) : "r"(addr));
}
static __device__ __forceinline__ void cp16(unsigned dst, const void* src) {
    asm volatile("cp.async.cg.shared.global [%0], [%1], 16;"
                 :: "r"(dst), "l"(src));
}
static __device__ __forceinline__ unsigned exp2_pack(float a, float b) {
    __half2 h = h2exp2(__floats2half2_rn(a, b));   // ex2.approx.f16x2
    return *reinterpret_cast<unsigned*>(&h);
}
#define CP_COMMIT() asm volatile("cp.async.commit_group;")
#define CP_WAIT(n)  asm volatile("cp.async.wait_group %0;" :: "n"(n))

// ---------------- fused prep kernel (single launch) ----------------
#define MASK4 (SEQ*SEQ/4)                    // 1048576
#define X4    (BATCH*SEQ*D_MODEL/4)          // 524288
#define W4    (3*D_MODEL*D_MODEL/4)          // 196608
#define NCP   (BATCH*NHEAD*SEQ)              // 32768
#define PREP_TOT (MASK4 + X4 + W4 + NCP)

__global__ void prep_kernel(const float* __restrict__ mask,
                            const float* __restrict__ x,
                            const float* __restrict__ w,
                            const float* __restrict__ coords,
                            const float* __restrict__ rw) {
    int i = blockIdx.x * blockDim.x + threadIdx.x;
    if (i < MASK4) {
        float4 m = ((const float4*)mask)[i];
        int q = i >> 9;                 // row (512 float4 per row)
        int c = (i & 511) * 4;          // col, multiple of 4
        int kt = c >> 6, r = c & 63;
        int j = r >> 3, t = (r & 7) >> 1;   // t in {0,2}; pair2 -> t+1
        __half2* dst = (__half2*)g_maskh + q*1024 + kt*32 + j;
        dst[t*8]       = __floats2half2_rn(m.x*LOG2E, m.y*LOG2E);
        dst[(t+1)*8]   = __floats2half2_rn(m.z*LOG2E, m.w*LOG2E);
        return;
    }
    i -= MASK4;
    if (i < X4) {
        float4 v = ((const float4*)x)[i];
        __half2* d = (__half2*)g_xh;
        d[i*2]     = __floats2half2_rn(v.x, v.y);
        d[i*2 + 1] = __floats2half2_rn(v.z, v.w);
        return;
    }
    i -= X4;
    if (i < W4) {
        float4 v = ((const float4*)w)[i];
        __half2* d = (__half2*)g_wh;
        d[i*2]     = __floats2half2_rn(v.x, v.y);
        d[i*2 + 1] = __floats2half2_rn(v.z, v.w);
        return;
    }
    i -= W4;
    if (i < NCP) {
        int n = i & (SEQ - 1);
        int h = (i >> 11) & 7;
        int b = i >> 14;
        const float* c = coords + (b*SEQ + n)*3;
        const float* wv = rw + h*3;
        g_cp[i] = (c[0]*wv[0] + c[1]*wv[1] + c[2]*wv[2]) * LOG2E;
    }
}

// ---------------- QKV GEMM: fp16 mma, cp.async double buffer ------------
#define GST 72
#define G_SMEM ((2*128*GST + 2*64*GST) * 2)     // 55296 bytes

__global__ __launch_bounds__(256)
void qkv_gemm_kernel(const float* __restrict__ bias) {
    extern __shared__ __align__(16) char smraw[];
    __half* Xs = (__half*)smraw;
    __half* Ws = (__half*)smraw + 2*128*GST;
    const int m0 = blockIdx.y * 128, o0 = blockIdx.x * 64;
    const int tid = threadIdx.x, lane = tid & 31, warp = tid >> 5;
    const int g = lane >> 2, t = lane & 3, wm = warp * 16;
    const int lrow = lane & 15, lcol = (lane >> 4) << 3;

    const __half* xg = g_xh + (size_t)m0 * D_MODEL;
    const __half* wg = g_wh + (size_t)o0 * D_MODEL;

    auto issue = [&](int ch, int stg) {
        int kb = ch * 64;
        #pragma unroll
        for (int s = 0; s < 4; s++) {
            int slot = tid + s*256;
            int row = slot >> 3, c8 = slot & 7;
            cp16(smem_u32(&Xs[stg*128*GST + row*GST + c8*8]),
                 xg + (size_t)row*D_MODEL + kb + c8*8);
        }
        #pragma unroll
        for (int s = 0; s < 2; s++) {
            int slot = tid + s*256;
            int row = slot >> 3, c8 = slot & 7;
            cp16(smem_u32(&Ws[stg*64*GST + row*GST + c8*8]),
                 wg + (size_t)row*D_MODEL + kb + c8*8);
        }
    };

    float c[8][4] = {};
    issue(0, 0); CP_COMMIT();

    for (int ch = 0; ch < 8; ch++) {
        int cb = ch & 1;
        if (ch < 7) { issue(ch + 1, cb ^ 1); CP_COMMIT(); CP_WAIT(1); }
        else        { CP_WAIT(0); }
        __syncthreads();
        const __half* X = Xs + cb*128*GST;
        const __half* W = Ws + cb*64*GST;
        #pragma unroll
        for (int kk = 0; kk < 4; kk++) {
            unsigned a[4];
            ldsm_x4(a[0], a[1], a[2], a[3],
                    smem_u32(&X[(wm + lrow)*GST + kk*16 + lcol]));
            #pragma unroll
            for (int j = 0; j < 4; j++) {
                unsigned r0, r1, r2, r3;
                ldsm_x4(r0, r1, r2, r3,
                        smem_u32(&W[(j*16 + lrow)*GST + kk*16 + lcol]));
                mma_f16(c[2*j],     a, r0, r2);
                mma_f16(c[2*j + 1], a, r1, r3);
            }
        }
        __syncthreads();
    }

    const int which = o0 >> 9;               // 0=q 1=k 2=v
    const int h = (o0 >> 6) & 7;
    const float sc = (which == 0) ? QSCALE : 1.0f;
    __half* dstbase = (which == 0) ? g_Q : (which == 1 ? g_K : g_V);
    #pragma unroll
    for (int r = 0; r < 2; r++) {
        int m = m0 + wm + g + r*8;
        int b = m >> 11, n = m & 2047;
        __half* dst = dstbase + ((size_t)(b*NHEAD + h)*SEQ + n)*HD;
        #pragma unroll
        for (int j = 0; j < 8; j++) {
            int c0 = j*8 + t*2;
            float2 bi = *(const float2*)&bias[o0 + c0];
            *(__half2*)&dst[c0] = __floats2half2_rn(
                (c[j][r*2 + 0] + bi.x) * sc,
                (c[j][r*2 + 1] + bi.y) * sc);
        }
    }
}

// ---------------- flash attention: Q in regs, 3-stage pipe, f16x2 exp ----
#define ST   72
#define NSTG 3
#define NT   (SEQ/64)
#define F_SMEM ((NSTG*128*ST)*2 + NSTG*64*4)   // 56064 bytes
#define ONE2 0x3C003C00u

__global__ __launch_bounds__(256, 2)
void flash_kernel(float* __restrict__ out) {
    extern __shared__ __align__(16) char smraw[];
    __half* KV  = (__half*)smraw;                  // NSTG * 128*ST
    float*  cpk = (float*)(KV + NSTG*128*ST);      // NSTG * 64

    const int b = blockIdx.z, h = blockIdx.y, q0 = blockIdx.x * 128;
    const int tid = threadIdx.x, lane = tid & 31, warp = tid >> 5;
    const int g = lane >> 2, t = lane & 3, wm = warp * 16;
    const int lrow = lane & 15, lcol = (lane >> 4) << 3;

    const size_t base = (size_t)(b*NHEAD + h) * SEQ;
    const __half* Qg  = g_Q + (base + q0) * HD;
    const __half* Kg  = g_K + base * HD;
    const __half* Vg  = g_V + base * HD;
    const float*  cpb = g_cp + base;

    // ---- stage Q through stage-0 smem, hoist fragments to registers ----
    #pragma unroll
    for (int s = 0; s < 4; s++) {
        int slot = tid + s*256;
        int row = slot >> 3, c8 = slot & 7;
        cp16(smem_u32(&KV[row*ST + c8*8]), Qg + (size_t)row*HD + c8*8);
    }
    CP_COMMIT(); CP_WAIT(0);
    __syncthreads();
    unsigned qa[4][4];
    #pragma unroll
    for (int kk = 0; kk < 4; kk++)
        ldsm_x4(qa[kk][0], qa[kk][1], qa[kk][2], qa[kk][3],
                smem_u32(&KV[(wm + lrow)*ST + kk*16 + lcol]));
    __syncthreads();

    auto issue_kv = [&](int kt, int stg) {
        int k0 = kt * 64;
        __half* Kh = KV + stg*128*ST;
        __half* Vh = Kh + 64*ST;
        #pragma unroll
        for (int s = 0; s < 2; s++) {
            int slot = tid + s*256;
            int row = slot >> 3, c8 = slot & 7;
            cp16(smem_u32(&Kh[row*ST + c8*8]), Kg + (size_t)(k0+row)*HD + c8*8);
            cp16(smem_u32(&Vh[row*ST + c8*8]), Vg + (size_t)(k0+row)*HD + c8*8);
        }
        if (tid < 16) cp16(smem_u32(&cpk[stg*64 + tid*4]), cpb + k0 + tid*4);
    };

    issue_kv(0, 0); CP_COMMIT();
    issue_kv(1, 1); CP_COMMIT();

    float o[8][4] = {};
    float l_acc[4] = {};
    float m_lo = -1e30f, m_hi = -1e30f;
    const int r_lo = q0 + wm + g;
    // fragment-ordered mask: base of this thread's lane column within a tile
    const __half* mrow_lo = g_maskh + (size_t)r_lo * SEQ + t*16;
    const __half* mrow_hi = g_maskh + (size_t)(r_lo + 8) * SEQ + t*16;

    for (int kt = 0; kt < NT; kt++) {
        const int stg = kt % NSTG;
        if (kt < NT - 1) { CP_WAIT(1); } else { CP_WAIT(0); }
        __syncthreads();                        // all done reading stage (kt-1)%3
        if (kt + 2 < NT) { issue_kv(kt + 2, (kt + 2) % NSTG); CP_COMMIT(); }

        // mask tile: 4x LDG.128, fragment-ordered (j packed along uint4 lanes)
        uint4 ml0 = *(const uint4*)(mrow_lo + kt*64);
        uint4 ml1 = *(const uint4*)(mrow_lo + kt*64 + 8);
        uint4 mh0 = *(const uint4*)(mrow_hi + kt*64);
        uint4 mh1 = *(const uint4*)(mrow_hi + kt*64 + 8);
        const unsigned* mlv = (const unsigned*)&ml0;   // [0..3]=j0..3, ml1 j4..7
        const unsigned* mhv = (const unsigned*)&mh0;

        const __half* K = KV + stg*128*ST;
        const __half* V = K + 64*ST;
        const float*  cp = cpk + stg*64;

        // ---- S = Q·K^T (Q frags in registers) ----
        float sreg[8][4] = {};
        #pragma unroll
        for (int kk = 0; kk < 4; kk++) {
            #pragma unroll
            for (int j = 0; j < 4; j++) {
                unsigned r0, r1, r2, r3;
                ldsm_x4(r0, r1, r2, r3,
                        smem_u32(&K[(j*16 + lrow)*ST + kk*16 + lcol]));
                mma_f16(sreg[2*j],     qa[kk], r0, r2);
                mma_f16(sreg[2*j + 1], qa[kk], r1, r3);
            }
        }

        // ---- bias: + mask(×LOG2E fp16) - cp_k ----
        #pragma unroll
        for (int j = 0; j < 8; j++) {
            unsigned mw_l = (j < 4) ? mlv[j] : ((const unsigned*)&ml1)[j-4];
            unsigned mw_h = (j < 4) ? mhv[j] : ((const unsigned*)&mh1)[j-4];
            float2 ml = __half22float2(*(const __half2*)&mw_l);
            float2 mh = __half22float2(*(const __half2*)&mw_h);
            float2 cpv = *(const float2*)&cp[j*8 + t*2];
            sreg[j][0] += ml.x - cpv.x;
            sreg[j][1] += ml.y - cpv.y;
            sreg[j][2] += mh.x - cpv.x;
            sreg[j][3] += mh.y - cpv.y;
        }

        // ---- online softmax: max (regs + quad shfl) ----
        float tl = -1e30f, th = -1e30f;
        #pragma unroll
        for (int j = 0; j < 8; j++) {
            tl = fmaxf(tl, fmaxf(sreg[j][0], sreg[j][1]));
            th = fmaxf(th, fmaxf(sreg[j][2], sreg[j][3]));
        }
        tl = fmaxf(tl, __shfl_xor_sync(0xffffffffu, tl, 1));
        tl = fmaxf(tl, __shfl_xor_sync(0xffffffffu, tl, 2));
        th = fmaxf(th, __shfl_xor_sync(0xffffffffu, th, 1));
        th = fmaxf(th, __shfl_xor_sync(0xffffffffu, th, 2));
        float mnl = fmaxf(m_lo, tl), mnh = fmaxf(m_hi, th);
        float al = exp2f(m_lo - mnl), ah = exp2f(m_hi - mnh);
        m_lo = mnl; m_hi = mnh;

        // ---- P = exp2(S-m) directly into packed fp16 A-fragments ----
        unsigned ph_lo[8], ph_hi[8];
        #pragma unroll
        for (int j = 0; j < 8; j++) {
            ph_lo[j] = exp2_pack(sreg[j][0] - mnl, sreg[j][1] - mnl);
            ph_hi[j] = exp2_pack(sreg[j][2] - mnh, sreg[j][3] - mnh);
            o[j][0] *= al; o[j][1] *= al; o[j][2] *= ah; o[j][3] *= ah;
        }
        l_acc[0] *= al; l_acc[1] *= al; l_acc[2] *= ah; l_acc[3] *= ah;

        // ---- O += P·V ; l += P·1 (ones-column mma) ----
        #pragma unroll
        for (int jp = 0; jp < 4; jp++) {
            unsigned pa[4] = { ph_lo[2*jp], ph_hi[2*jp],
                               ph_lo[2*jp+1], ph_hi[2*jp+1] };
            #pragma unroll
            for (int np = 0; np < 4; np++) {
                unsigned r0, r1, r2, r3;
                ldsm_x4t(r0, r1, r2, r3,
                         smem_u32(&V[(jp*16 + lrow)*ST + np*16 + lcol]));
                mma_f16(o[2*np],     pa, r0, r1);
                mma_f16(o[2*np + 1], pa, r2, r3);
            }
            mma_f16(l_acc, pa, ONE2, ONE2);
        }
        // no end-of-tile sync: next iteration's start sync fences reuse
    }

    // ---- epilogue ----
    float il = 1.f / l_acc[0], ih = 1.f / l_acc[2];
    #pragma unroll
    for (int j = 0; j < 8; j++) {
        float2 v0 = { o[j][0]*il, o[j][1]*il };
        float2 v1 = { o[j][2]*ih, o[j][3]*ih };
        size_t off = ((size_t)b*SEQ + r_lo)*D_MODEL + h*HD + j*8 + t*2;
        *(float2*)&out[off] = v0;
        *(float2*)&out[off + 8*D_MODEL] = v1;
    }
}

// ---------------- launch ----------------
extern "C" void kernel_launch(void* const* d_in, const int* in_sizes, int n_in,
                              void* d_out, int out_size) {
    const float* x      = (const float*)d_in[0];
    const float* coords = (const float*)d_in[1];
    const float* mask   = (const float*)d_in[2];
    const float* qkv_w  = (const float*)d_in[3];
    const float* qkv_b  = (const float*)d_in[4];
    const float* rw     = (const float*)d_in[5];
    float* out = (float*)d_out;

    prep_kernel<<<(PREP_TOT + 255)/256, 256>>>(mask, x, qkv_w, coords, rw);

    cudaFuncSetAttribute(qkv_gemm_kernel,
                         cudaFuncAttributeMaxDynamicSharedMemorySize, G_SMEM);
    dim3 ggrid(3*D_MODEL/64, BATCH*SEQ/128);
    qkv_gemm_kernel<<<ggrid, 256, G_SMEM>>>(qkv_b);

    cudaFuncSetAttribute(flash_kernel,
                         cudaFuncAttributeMaxDynamicSharedMemorySize, F_SMEM);
    dim3 fgrid(SEQ/128, NHEAD, BATCH);
    flash_kernel<<<fgrid, 256, F_SMEM>>>(out);
}